// round 15
// baseline (speedup 1.0000x reference)
#include <cuda_runtime.h>
#include <math.h>

#define Bn 4
#define Tn 8192
#define Dn 512
#define Sn 16
#define PARTS 64   // 256 blocks / 4 batches in the fused attn+G pass

// Scratch (static device globals — allocation-free per harness rules)
__device__ float g_attn [Bn*Tn*Sn];          // 2 MB
__device__ float g_Gpart[Bn*PARTS*Sn*Dn];    // 8 MB
__device__ float g_G    [Bn*Sn*Dn];
__device__ float g_Wf   [Dn*Dn];             // 1 MB: Wf = Wo . Wv
__device__ float g_M    [Bn*Sn*Dn];

__device__ __forceinline__ unsigned f2tf32(float f) {
    unsigned r; asm("cvt.rna.tf32.f32 %0, %1;" : "=r"(r) : "f"(f));
    return r;
}

__device__ __forceinline__ float4 tf32x4(float4 v) {
    float4 t;
    t.x = __uint_as_float(f2tf32(v.x));
    t.y = __uint_as_float(f2tf32(v.y));
    t.z = __uint_as_float(f2tf32(v.z));
    t.w = __uint_as_float(f2tf32(v.w));
    return t;
}

__device__ __forceinline__ void mma_tf32(float c[4],
    unsigned a0, unsigned a1, unsigned a2, unsigned a3,
    unsigned b0, unsigned b1) {
    asm("mma.sync.aligned.m16n8k8.row.col.f32.tf32.tf32.f32 "
        "{%0,%1,%2,%3}, {%4,%5,%6,%7}, {%8,%9}, {%0,%1,%2,%3};"
        : "+f"(c[0]), "+f"(c[1]), "+f"(c[2]), "+f"(c[3])
        : "r"(a0), "r"(a1), "r"(a2), "r"(a3), "r"(b0), "r"(b1));
}

// 8-lane reduction (lanes differing in bits 0..2)
__device__ __forceinline__ float red8(float v) {
    v += __shfl_xor_sync(0xffffffffu, v, 1);
    v += __shfl_xor_sync(0xffffffffu, v, 2);
    v += __shfl_xor_sync(0xffffffffu, v, 4);
    return v;
}

// Reduce acc[16] with 16 shuffles; result for index (lane>>1)&15 on even lanes.
__device__ __forceinline__ float reduce16_scatter(float* acc, int lane) {
#pragma unroll
    for (int step = 16, n = 8; n >= 1; step >>= 1, n >>= 1) {
        bool hi = (lane & step) != 0;
#pragma unroll
        for (int i = 0; i < n; i++) {
            float send = hi ? acc[i] : acc[i + n];
            float recv = __shfl_xor_sync(0xffffffffu, send, step);
            acc[i] = (hi ? acc[i + n] : acc[i]) + recv;
        }
    }
    float v = acc[0];
    v += __shfl_xor_sync(0xffffffffu, v, 1);
    return v;
}

// ---------------------------------------------------------------------------
// Kernel 1 (fused): blocks 0..255: attention weights (tf32 MMA, pipelined
// staging, x2 folded) + partial G = attn^T x (fp32). Blocks 256..287: Wf =
// Wo . Wv via tf32 MMA (128x64 tile each), overlapped — 288 blocks = 1 wave.
// ---------------------------------------------------------------------------
__global__ __launch_bounds__(256, 2) void k_attn_g(const float* __restrict__ x,
                                                   const float* __restrict__ centers,
                                                   const float* __restrict__ log_scales,
                                                   const float* __restrict__ Wv,
                                                   const float* __restrict__ Wo) {
    __shared__ float    s_x   [2][128 * 36]; // tf32 x chunks, padded (36 KB)
    __shared__ unsigned s_bf  [2][512];      // B fragments (centers) (4 KB)
    __shared__ float    s_xc  [128 * 17];    // XC, padded (8.7 KB)
    __shared__ float    s_attn[128 * Sn];    // 8 KB
    __shared__ float    s_x2  [128];
    __shared__ float    s_part[256];
    __shared__ float    s_inv [Sn], s_bias[Sn];

    int tid  = threadIdx.x;
    int warp = tid >> 5, lane = tid & 31;
    int gid  = lane >> 2, tg = lane & 3;     // mma fragment coords
    int tlw  = warp * 16;                    // warp's m-tile base
    int srow = (tid >> 3), sc4 = tid & 7;    // staging coords

    // =============== Wf blocks: Wf = Wo . Wv (tf32 MMA) ===============
    if (blockIdx.x >= 256) {
        int wfb  = blockIdx.x - 256;         // 0..31
        int row0 = (wfb & 3) * 128;          // Wo row stripe
        int col0 = (wfb >> 2) * 64;          // Wv col stripe
        float* s_wo = s_x[0];                // 128 x 36 (reuse)
        float* s_wv = s_xc;                  // 32 x 68 = 2176 floats (reuse)

        float cw[8][4];
#pragma unroll
        for (int n = 0; n < 8; n++)
#pragma unroll
            for (int r = 0; r < 4; r++) cw[n][r] = 0.f;

#pragma unroll 1
        for (int c = 0; c < 16; c++) {
#pragma unroll
            for (int i = 0; i < 4; i++) {
                int row = srow + i * 32;
                float4 v = ((const float4*)(Wo + (long long)(row0 + row) * Dn))[c * 8 + sc4];
                *(float4*)&s_wo[row * 36 + sc4 * 4] = tf32x4(v);
            }
#pragma unroll
            for (int i = 0; i < 2; i++) {
                int idx = tid + i * 256;     // 0..511 = 32 rows x 16 float4
                int e = idx >> 4, j4 = idx & 15;
                float4 v = ((const float4*)(Wv + (long long)(c * 32 + e) * Dn + col0))[j4];
                *(float4*)&s_wv[e * 68 + j4 * 4] = tf32x4(v);
            }
            __syncthreads();
#pragma unroll
            for (int kit8 = 0; kit8 < 4; kit8++) {
                int kb = kit8 * 8;
                unsigned a0 = __float_as_uint(s_wo[(tlw + gid)     * 36 + kb + tg]);
                unsigned a1 = __float_as_uint(s_wo[(tlw + gid + 8) * 36 + kb + tg]);
                unsigned a2 = __float_as_uint(s_wo[(tlw + gid)     * 36 + kb + tg + 4]);
                unsigned a3 = __float_as_uint(s_wo[(tlw + gid + 8) * 36 + kb + tg + 4]);
#pragma unroll
                for (int nch = 0; nch < 8; nch++) {
                    unsigned b0 = __float_as_uint(s_wv[(kb + tg)     * 68 + nch * 8 + gid]);
                    unsigned b1 = __float_as_uint(s_wv[(kb + tg + 4) * 68 + nch * 8 + gid]);
                    mma_tf32(cw[nch], a0, a1, a2, a3, b0, b1);
                }
            }
            __syncthreads();
        }
#pragma unroll
        for (int nch = 0; nch < 8; nch++) {
            int r0 = row0 + tlw + gid;
            int cc = col0 + nch * 8 + tg * 2;
            g_Wf[(long long)r0       * Dn + cc]     = cw[nch][0];
            g_Wf[(long long)r0       * Dn + cc + 1] = cw[nch][1];
            g_Wf[(long long)(r0 + 8) * Dn + cc]     = cw[nch][2];
            g_Wf[(long long)(r0 + 8) * Dn + cc + 1] = cw[nch][3];
        }
        return;
    }

    // =============== attention blocks (round-13 measured-best) ===============
    long long tok0 = (long long)blockIdx.x * 128;
    const float* xb = x + tok0 * Dn;

    // ---- scale/bias precompute: c2 via 16 threads per splat ----
    {
        int sp = tid >> 4, p16 = tid & 15;
        const float4* cr = (const float4*)(centers + (long long)sp * Dn);
        float c2 = 0.f;
#pragma unroll
        for (int j = 0; j < 8; j++) {
            float4 v = cr[p16 + j * 16];
            c2 += v.x * v.x + v.y * v.y + v.z * v.z + v.w * v.w;
        }
        s_part[tid] = c2;
        __syncthreads();
        if (tid < Sn) {
            float c2t = 0.f;
#pragma unroll
            for (int k = 0; k < 16; k++) c2t += s_part[tid * 16 + k];
            float s = expf(log_scales[tid]);
            s = fminf(fmaxf(s, 0.1f), 2.0f);
            float inv = -0.5f / (s * s);
            s_inv[tid]  = inv;
            s_bias[tid] = inv * c2t;
        }
    }

    // ---- Phase 1: XC = x . centers^T via tf32 mma, pipelined staging ----
    float xcacc[2][4];
#pragma unroll
    for (int h = 0; h < 2; h++)
#pragma unroll
        for (int r = 0; r < 4; r++) xcacc[h][r] = 0.f;
    float x2p[4] = {0.f, 0.f, 0.f, 0.f};

    float4   pre[4];
    unsigned preb[2];
    int pe[2];
#pragma unroll
    for (int i = 0; i < 2; i++) pe[i] = tid + i * 256;

    // --- prologue: load chunk 0 ---
#pragma unroll
    for (int i = 0; i < 4; i++)
        pre[i] = ((const float4*)(xb + (long long)(srow + i * 32) * Dn))[sc4];
#pragma unroll
    for (int i = 0; i < 2; i++) {
        int e = pe[i];
        int kit8 = e >> 7, rem = e & 127;
        int h = rem >> 6, which = (rem >> 5) & 1, L = rem & 31;
        int k  = kit8 * 8 + (L & 3) + which * 4;
        int sp = h * 8 + (L >> 2);
        preb[i] = f2tf32(centers[(long long)sp * Dn + k]);
    }
#pragma unroll
    for (int i = 0; i < 4; i++) {
        float4 v = pre[i];
        x2p[i] += v.x * v.x + v.y * v.y + v.z * v.z + v.w * v.w;
        *(float4*)&s_x[0][(srow + i * 32) * 36 + sc4 * 4] = tf32x4(v);
    }
#pragma unroll
    for (int i = 0; i < 2; i++) s_bf[0][pe[i]] = preb[i];
    __syncthreads();

#pragma unroll 1
    for (int c = 0; c < 16; c++) {
        int cur = c & 1;
        if (c < 15) {
#pragma unroll
            for (int i = 0; i < 4; i++)
                pre[i] = ((const float4*)(xb + (long long)(srow + i * 32) * Dn))[(c + 1) * 8 + sc4];
#pragma unroll
            for (int i = 0; i < 2; i++) {
                int e = pe[i];
                int kit8 = e >> 7, rem = e & 127;
                int h = rem >> 6, which = (rem >> 5) & 1, L = rem & 31;
                int k  = (c + 1) * 32 + kit8 * 8 + (L & 3) + which * 4;
                int sp = h * 8 + (L >> 2);
                preb[i] = f2tf32(centers[(long long)sp * Dn + k]);
            }
        }
#pragma unroll
        for (int kit8 = 0; kit8 < 4; kit8++) {
            int kb = kit8 * 8;
            unsigned a0 = __float_as_uint(s_x[cur][(tlw + gid)     * 36 + kb + tg]);
            unsigned a1 = __float_as_uint(s_x[cur][(tlw + gid + 8) * 36 + kb + tg]);
            unsigned a2 = __float_as_uint(s_x[cur][(tlw + gid)     * 36 + kb + tg + 4]);
            unsigned a3 = __float_as_uint(s_x[cur][(tlw + gid + 8) * 36 + kb + tg + 4]);
#pragma unroll
            for (int h = 0; h < 2; h++) {
                unsigned b0 = s_bf[cur][kit8 * 128 + h * 64 + lane];
                unsigned b1 = s_bf[cur][kit8 * 128 + h * 64 + 32 + lane];
                mma_tf32(xcacc[h], a0, a1, a2, a3, b0, b1);
            }
        }
        if (c < 15) {
            int nxt = cur ^ 1;
#pragma unroll
            for (int i = 0; i < 4; i++) {
                float4 v = pre[i];
                x2p[i] += v.x * v.x + v.y * v.y + v.z * v.z + v.w * v.w;
                *(float4*)&s_x[nxt][(srow + i * 32) * 36 + sc4 * 4] = tf32x4(v);
            }
#pragma unroll
            for (int i = 0; i < 2; i++) s_bf[nxt][pe[i]] = preb[i];
        }
        __syncthreads();
    }

    // write XC fragments to padded smem
#pragma unroll
    for (int h = 0; h < 2; h++) {
        int col = h * 8 + tg * 2;
        s_xc[(tlw + gid)     * 17 + col]     = xcacc[h][0];
        s_xc[(tlw + gid)     * 17 + col + 1] = xcacc[h][1];
        s_xc[(tlw + gid + 8) * 17 + col]     = xcacc[h][2];
        s_xc[(tlw + gid + 8) * 17 + col + 1] = xcacc[h][3];
    }
    // finish x2
#pragma unroll
    for (int i = 0; i < 4; i++) {
        float v = red8(x2p[i]);
        if ((tid & 7) == 0) s_x2[(tid >> 3) + i * 32] = v;
    }
    __syncthreads();

    // per-token softmax (threads 0..127)
    if (tid < 128) {
        float x2 = s_x2[tid];
        float l[Sn];
        float m = -1e30f;
#pragma unroll
        for (int s = 0; s < Sn; s++) {
            l[s] = s_inv[s] * (x2 - 2.f * s_xc[tid * 17 + s]) + s_bias[s];
            m = fmaxf(m, l[s]);
        }
        float sum = 0.f;
#pragma unroll
        for (int s = 0; s < Sn; s++) { l[s] = __expf(l[s] - m); sum += l[s]; }
        float r = 1.f / sum;
#pragma unroll
        for (int s = 0; s < Sn; s++) s_attn[tid * Sn + s] = l[s] * r;
    }
    __syncthreads();

    // coalesced copy s_attn -> g_attn
    for (int i = tid; i < 128 * Sn / 4; i += 256)
        ((float4*)(g_attn + tok0 * Sn))[i] = ((const float4*)s_attn)[i];

    // -------- Phase 2: G partial over this block's 128 tokens (fp32) --------
    float2 accG[Sn];
#pragma unroll
    for (int s = 0; s < Sn; s++) { accG[s].x = 0.f; accG[s].y = 0.f; }

#pragma unroll 8
    for (int t = 0; t < 128; t++) {
        float2 xv = ((const float2*)(xb + (long long)t * Dn))[tid];   // d = 2*tid, 2*tid+1
        const float4* ar = (const float4*)&s_attn[t * Sn];
#pragma unroll
        for (int q = 0; q < 4; q++) {
            float4 a = ar[q];
            accG[q*4+0].x += a.x * xv.x; accG[q*4+0].y += a.x * xv.y;
            accG[q*4+1].x += a.y * xv.x; accG[q*4+1].y += a.y * xv.y;
            accG[q*4+2].x += a.z * xv.x; accG[q*4+2].y += a.z * xv.y;
            accG[q*4+3].x += a.w * xv.x; accG[q*4+3].y += a.w * xv.y;
        }
    }

    int b = (int)(tok0 / Tn);
    int p = (int)((tok0 % Tn) / 128);
    float* gp = g_Gpart + ((long long)(b * PARTS + p) * Sn * Dn);
#pragma unroll
    for (int s = 0; s < Sn; s++)
        ((float2*)(gp + s * Dn))[tid] = accG[s];
}

// ---------------------------------------------------------------------------
// Kernel 2: reduce 64 partials -> G. 32768 outputs. Grid 128 x 256 thr.
// ---------------------------------------------------------------------------
__global__ void k_reduce() {
    int idx = blockIdx.x * blockDim.x + threadIdx.x;   // < Bn*Sn*Dn = 32768
    int b = idx >> 13;
    int r = idx & 8191;
    float sum = 0.f;
#pragma unroll
    for (int p = 0; p < PARTS; p++)
        sum += g_Gpart[(long long)(b * PARTS + p) * (Sn * Dn) + r];
    g_G[idx] = sum;
}

// ---------------------------------------------------------------------------
// Kernel 3: single small GEMM M[row][k] = sum_d G[row][d] * Wf[k][d], rows=64.
// Round-6 measured-best body: grid (64,4) x 256 thr, 16 in-rows in smem,
// warp-per-column, plain float4 FMA, reduce-scatter finish.
// ---------------------------------------------------------------------------
__global__ __launch_bounds__(256) void k_small_gemm() {
    __shared__ float4 s_in[16 * 128];        // 32 KB

    int tid = threadIdx.x, warp = tid >> 5, lane = tid & 31;
    int kc = blockIdx.x;                     // 0..63 column chunk
    int b  = blockIdx.y;                     // 0..3 batch

    const float4* src = (const float4*)(g_G + (long long)b * 16 * Dn);
#pragma unroll
    for (int i = 0; i < 8; i++) s_in[tid + i * 256] = src[tid + i * 256];
    __syncthreads();

    int k = kc * 8 + warp;                   // output column, 0..511
    const float4* wr = (const float4*)(g_Wf + (long long)k * Dn);
    float4 w0 = wr[lane], w1 = wr[lane + 32], w2 = wr[lane + 64], w3 = wr[lane + 96];

    float acc[16];
#pragma unroll
    for (int r = 0; r < 16; r++) {
        float4 g0 = s_in[r * 128 + lane];
        float4 g1 = s_in[r * 128 + lane + 32];
        float4 g2 = s_in[r * 128 + lane + 64];
        float4 g3 = s_in[r * 128 + lane + 96];
        acc[r] = w0.x*g0.x + w0.y*g0.y + w0.z*g0.z + w0.w*g0.w
               + w1.x*g1.x + w1.y*g1.y + w1.z*g1.z + w1.w*g1.w
               + w2.x*g2.x + w2.y*g2.y + w2.z*g2.z + w2.w*g2.w
               + w3.x*g3.x + w3.y*g3.y + w3.z*g3.z + w3.w*g3.w;
    }
    float val = reduce16_scatter(acc, lane);
    int row = (lane >> 1) & 15;
    if ((lane & 1) == 0)
        g_M[(long long)(b * 16 + row) * Dn + k] = val;
}

// ---------------------------------------------------------------------------
// Kernel 4: y = attn . M via tf32 MMA, D split in halves for occupancy.
// Grid (256 token tiles, 2 D-halves) x 256 thr. Block stages attn (8 KB) +
// half of M (16x256 tf32, padded stride 264, 16.9 KB). Warp: 16-token m-tile,
// 32 n-chunks of 8 dims, k = 16 splats (2 k-steps).
// ---------------------------------------------------------------------------
__global__ __launch_bounds__(256) void k_out(float* __restrict__ y) {
    __shared__ float s_a[128 * Sn];          // attn tile as tf32 (8 KB)
    __shared__ float s_m[16 * 264];          // M half-tile as tf32, padded (16.9 KB)
    int tid = threadIdx.x, warp = tid >> 5, lane = tid & 31;
    int gid = lane >> 2, tg = lane & 3;
    long long tok0 = (long long)blockIdx.x * 128;
    int dh = blockIdx.y;                     // D half: 0 or 1
    int dbase = dh * 256;
    int b = (int)(tok0 / Tn);

    // stage attn as tf32 (coalesced float4)
#pragma unroll
    for (int i = 0; i < 2; i++) {
        float4 v = ((const float4*)(g_attn + tok0 * Sn))[tid + i * 256];
        ((float4*)s_a)[tid + i * 256] = tf32x4(v);
    }
    // stage M half (cols dbase..dbase+255) as tf32, padded stride 264
    const float* Mb = g_M + (long long)b * Sn * Dn + dbase;
#pragma unroll
    for (int i = 0; i < 4; i++) {
        int e = tid + i * 256;               // 0..1023 = 16 rows x 64 float4
        int r = e >> 6, c4 = e & 63;
        float4 v = ((const float4*)(Mb + (long long)r * Dn))[c4];
        *(float4*)&s_m[r * 264 + c4 * 4] = tf32x4(v);
    }
    __syncthreads();

    int tlw = warp * 16;                     // warp's 16-token m-tile
    unsigned a00 = __float_as_uint(s_a[(tlw + gid)     * Sn + tg]);
    unsigned a01 = __float_as_uint(s_a[(tlw + gid + 8) * Sn + tg]);
    unsigned a02 = __float_as_uint(s_a[(tlw + gid)     * Sn + tg + 4]);
    unsigned a03 = __float_as_uint(s_a[(tlw + gid + 8) * Sn + tg + 4]);
    unsigned a10 = __float_as_uint(s_a[(tlw + gid)     * Sn + tg + 8]);
    unsigned a11 = __float_as_uint(s_a[(tlw + gid + 8) * Sn + tg + 8]);
    unsigned a12 = __float_as_uint(s_a[(tlw + gid)     * Sn + tg + 12]);
    unsigned a13 = __float_as_uint(s_a[(tlw + gid + 8) * Sn + tg + 12]);

    float* y0 = y + (tok0 + tlw + gid)     * Dn + dbase + 2 * tg;
    float* y1 = y + (tok0 + tlw + gid + 8) * Dn + dbase + 2 * tg;

#pragma unroll 4
    for (int d0 = 0; d0 < 256; d0 += 8) {
        float c[4] = {0.f, 0.f, 0.f, 0.f};
        unsigned b00 = __float_as_uint(s_m[ tg      * 264 + d0 + gid]);
        unsigned b01 = __float_as_uint(s_m[(tg + 4) * 264 + d0 + gid]);
        mma_tf32(c, a00, a01, a02, a03, b00, b01);
        unsigned b10 = __float_as_uint(s_m[(tg + 8)  * 264 + d0 + gid]);
        unsigned b11 = __float_as_uint(s_m[(tg + 12) * 264 + d0 + gid]);
        mma_tf32(c, a10, a11, a12, a13, b10, b11);
        *(float2*)(y0 + d0) = make_float2(c[0], c[1]);
        *(float2*)(y1 + d0) = make_float2(c[2], c[3]);
    }
}

// ---------------------------------------------------------------------------
extern "C" void kernel_launch(void* const* d_in, const int* in_sizes, int n_in,
                              void* d_out, int out_size) {
    (void)in_sizes; (void)n_in; (void)out_size;
    const float* x          = (const float*)d_in[0];   // [B,T,D]
    const float* centers    = (const float*)d_in[1];   // [S,D]
    const float* log_scales = (const float*)d_in[2];   // [S]
    const float* Wv         = (const float*)d_in[3];   // [D,D]
    const float* Wo         = (const float*)d_in[4];   // [D,D]
    float* y = (float*)d_out;                          // [B,T,D] fp32

    k_attn_g<<<288, 256>>>(x, centers, log_scales, Wv, Wo);
    k_reduce<<<128, 256>>>();
    k_small_gemm<<<dim3(64, 4), 256>>>();
    k_out<<<dim3(256, 2), 256>>>(y);
}